// round 3
// baseline (speedup 1.0000x reference)
#include <cuda_runtime.h>
#include <cuda_bf16.h>
#include <float.h>
#include <stdint.h>

#define N_NODES 50000
#define N_EDGES 640000
#define D       128
#define OUTF    128
#define K2      256   // 2*D concat width

// ---------------- device scratch (no allocations allowed) ----------------
__device__ __align__(16) float    g_h[N_NODES * D];      // fc_pool output
__device__ __align__(16) unsigned g_neigh[N_NODES * D];  // max-reduced messages (ordered-uint)
__device__ __align__(16) float    g_WtP[D * D];          // W_pool transposed: [k][j]
__device__ __align__(16) float    g_WtN[K2 * OUTF];      // W_neigh transposed: [k][j]

// monotonic float->uint transform: order-preserving for all finite floats
__device__ __forceinline__ unsigned f2ord(float f) {
    unsigned u = __float_as_uint(f);
    return (u & 0x80000000u) ? ~u : (u | 0x80000000u);
}
__device__ __forceinline__ float ord2f(unsigned u) {
    unsigned b = (u & 0x80000000u) ? (u & 0x7FFFFFFFu) : ~u;
    return __uint_as_float(b);
}
#define NEG_FLT_MAX_ORD 0x00800000u   // f2ord(-FLT_MAX) == sentinel for "no incoming edges"

// ---------------- prep: transpose weights ----------------
__global__ void prep_kernel(const float* __restrict__ Wp, const float* __restrict__ Wn) {
    int i = blockIdx.x * blockDim.x + threadIdx.x;
    if (i < D * D) {                    // Wp is [D][D] row-major: Wp[j*D+k]
        int j = i / D, k = i % D;
        g_WtP[k * D + j] = Wp[i];
    }
    if (i < OUTF * K2) {                // Wn is [OUTF][K2] row-major: Wn[j*K2+k]
        int j = i / K2, k = i % K2;
        g_WtN[k * OUTF + j] = Wn[i];
    }
}

// ---------------- init neigh buffer to sentinel ----------------
__global__ void init_neigh_kernel() {
    int i = blockIdx.x * blockDim.x + threadIdx.x;
    uint4* p = reinterpret_cast<uint4*>(g_neigh);
    const int n4 = (N_NODES * D) / 4;
    uint4 v = make_uint4(NEG_FLT_MAX_ORD, NEG_FLT_MAX_ORD, NEG_FLT_MAX_ORD, NEG_FLT_MAX_ORD);
    for (; i < n4; i += gridDim.x * blockDim.x) p[i] = v;
}

// ---------------- GEMM1: h = feat @ W_pool^T + b_pool ----------------
__global__ __launch_bounds__(128) void gemm1_kernel(const float* __restrict__ feat,
                                                    const float* __restrict__ bias) {
    __shared__ float sf[8][D];
    const int tid  = threadIdx.x;
    const int row0 = blockIdx.x * 8;
    #pragma unroll
    for (int r = 0; r < 8; r++) {
        int row = row0 + r;
        sf[r][tid] = (row < N_NODES) ? feat[row * D + tid] : 0.f;
    }
    __syncthreads();
    float acc[8];
    float bb = bias[tid];
    #pragma unroll
    for (int r = 0; r < 8; r++) acc[r] = bb;
    #pragma unroll 4
    for (int k = 0; k < D; k++) {
        float w = g_WtP[k * D + tid];
        #pragma unroll
        for (int r = 0; r < 8; r++) acc[r] = fmaf(sf[r][k], w, acc[r]);
    }
    #pragma unroll
    for (int r = 0; r < 8; r++) {
        int row = row0 + r;
        if (row < N_NODES) g_h[row * D + tid] = acc[r];
    }
}

// ---------------- edge pass: scatter-max of h[src]*w into neigh[dst] ----------------
// one warp per edge; lane handles 4 contiguous floats (float4 gather, 4 u32 RED.MAX)
__global__ __launch_bounds__(256) void edge_kernel(const int* __restrict__ src,
                                                   const int* __restrict__ dst,
                                                   const float* __restrict__ weight) {
    int gtid = blockIdx.x * blockDim.x + threadIdx.x;
    int e    = gtid >> 5;
    int lane = gtid & 31;
    if (e >= N_EDGES) return;
    int s = src[e];
    int d = dst[e];
    // defensive clamp: converts any input-format surprise into a rel_err signal, not a crash
    s = min(max(s, 0), N_NODES - 1);
    d = min(max(d, 0), N_NODES - 1);
    float w = weight[e];
    const float4* hp = reinterpret_cast<const float4*>(g_h + s * D);
    float4 v = hp[lane];
    unsigned* np = g_neigh + d * D + lane * 4;
    atomicMax(np + 0, f2ord(v.x * w));
    atomicMax(np + 1, f2ord(v.y * w));
    atomicMax(np + 2, f2ord(v.z * w));
    atomicMax(np + 3, f2ord(v.w * w));
}

// ---------------- GEMM2: out = concat(feat, neigh) @ W_neigh^T + b_neigh ----------------
__global__ __launch_bounds__(128) void gemm2_kernel(const float* __restrict__ feat,
                                                    const float* __restrict__ bias,
                                                    float* __restrict__ out) {
    __shared__ float sf[8][K2];
    const int tid  = threadIdx.x;
    const int row0 = blockIdx.x * 8;
    #pragma unroll
    for (int r = 0; r < 8; r++) {
        int row = row0 + r;
        if (row < N_NODES) {
            sf[r][tid] = feat[row * D + tid];
            unsigned u = g_neigh[row * D + tid];
            sf[r][D + tid] = (u == NEG_FLT_MAX_ORD) ? 0.f : ord2f(u);
        } else {
            sf[r][tid] = 0.f;
            sf[r][D + tid] = 0.f;
        }
    }
    __syncthreads();
    float acc[8];
    float bb = bias[tid];
    #pragma unroll
    for (int r = 0; r < 8; r++) acc[r] = bb;
    #pragma unroll 4
    for (int k = 0; k < K2; k++) {
        float w = g_WtN[k * OUTF + tid];
        #pragma unroll
        for (int r = 0; r < 8; r++) acc[r] = fmaf(sf[r][k], w, acc[r]);
    }
    #pragma unroll
    for (int r = 0; r < 8; r++) {
        int row = row0 + r;
        if (row < N_NODES) out[row * OUTF + tid] = acc[r];
    }
}

// ---------------- launch ----------------
extern "C" void kernel_launch(void* const* d_in, const int* in_sizes, int n_in,
                              void* d_out, int out_size) {
    const float* feat    = (const float*)d_in[0];
    const float* weight  = (const float*)d_in[1];
    const int*   src     = (const int*)d_in[2];   // JAX x64 disabled -> int32
    const int*   dst     = (const int*)d_in[3];
    const float* W_pool  = (const float*)d_in[4];
    const float* b_pool  = (const float*)d_in[5];
    const float* W_neigh = (const float*)d_in[6];
    const float* b_neigh = (const float*)d_in[7];
    float*       out     = (float*)d_out;

    prep_kernel<<<(OUTF * K2 + 255) / 256, 256>>>(W_pool, W_neigh);
    init_neigh_kernel<<<2048, 256>>>();

    gemm1_kernel<<<(N_NODES + 7) / 8, 128>>>(feat, b_pool);

    edge_kernel<<<(N_EDGES * 32 + 255) / 256, 256>>>(src, dst, weight);

    gemm2_kernel<<<(N_NODES + 7) / 8, 128>>>(feat, b_neigh, out);
}

// round 4
// speedup vs baseline: 1.8156x; 1.8156x over previous
#include <cuda_runtime.h>
#include <float.h>
#include <stdint.h>

#define N_NODES 50000
#define N_EDGES 640000
#define D       128
#define OUTF    128
#define K2      256
#define TM      128        // GEMM M-tile
#define PADW    132        // 128 + 4 pad (stride mult of 4 words -> 16B-aligned v4 LDS)

// ---------------- device scratch ----------------
__device__ __align__(16) float g_h[N_NODES * D];       // fc_pool output
__device__ __align__(16) float g_neigh[N_NODES * D];   // max-pooled messages (plain float)
__device__ int   g_deg[N_NODES];
__device__ int   g_start[N_NODES + 1];
__device__ int   g_cursor[N_NODES];
__device__ __align__(16) int   g_ssrc[N_EDGES];        // dst-sorted src ids
__device__ __align__(16) float g_sw[N_EDGES];          // dst-sorted edge weights

__device__ __forceinline__ int clampN(int v) { return min(max(v, 0), N_NODES - 1); }

// ---------------- CSR build ----------------
__global__ void zero_deg_kernel() {
    int i = blockIdx.x * blockDim.x + threadIdx.x;
    if (i < N_NODES) g_deg[i] = 0;
}

__global__ void hist_kernel(const int* __restrict__ dst) {
    int e = blockIdx.x * blockDim.x + threadIdx.x;
    if (e < N_EDGES) atomicAdd(&g_deg[clampN(dst[e])], 1);
}

// single-block exclusive scan over 50K degrees (1024 threads, Hillis-Steele chunks)
__global__ void scan_kernel() {
    __shared__ int sh[1024];
    __shared__ int s_carry;
    int tid = threadIdx.x;
    if (tid == 0) s_carry = 0;
    __syncthreads();
    for (int base = 0; base < N_NODES; base += 1024) {
        int idx = base + tid;
        int v = (idx < N_NODES) ? g_deg[idx] : 0;
        sh[tid] = v;
        __syncthreads();
        #pragma unroll
        for (int off = 1; off < 1024; off <<= 1) {
            int t = (tid >= off) ? sh[tid - off] : 0;
            __syncthreads();
            sh[tid] += t;
            __syncthreads();
        }
        int excl = sh[tid] - v;
        int c = s_carry;
        if (idx < N_NODES) { g_start[idx] = c + excl; g_cursor[idx] = c + excl; }
        __syncthreads();
        if (tid == 1023) s_carry = c + sh[1023];
        __syncthreads();
    }
    if (tid == 0) g_start[N_NODES] = s_carry;
}

__global__ void scatter_kernel(const int* __restrict__ src, const int* __restrict__ dst,
                               const float* __restrict__ weight) {
    int e = blockIdx.x * blockDim.x + threadIdx.x;
    if (e >= N_EDGES) return;
    int d = clampN(dst[e]);
    int pos = atomicAdd(&g_cursor[d], 1);
    g_ssrc[pos] = clampN(src[e]);
    g_sw[pos]   = weight[e];
}

// ---------------- per-node max reduce (no atomics) ----------------
// one block of 128 threads per dst node; thread owns one feature lane
__global__ __launch_bounds__(128) void reduce_kernel() {
    int node = blockIdx.x;
    int tid  = threadIdx.x;
    int beg = g_start[node], end = g_start[node + 1];
    float acc = -FLT_MAX;
    int i = beg;
    for (; i + 4 <= end; i += 4) {               // MLP = 4
        int   s0 = g_ssrc[i],   s1 = g_ssrc[i+1], s2 = g_ssrc[i+2], s3 = g_ssrc[i+3];
        float w0 = g_sw[i],     w1 = g_sw[i+1],   w2 = g_sw[i+2],   w3 = g_sw[i+3];
        float v0 = g_h[s0*D + tid], v1 = g_h[s1*D + tid];
        float v2 = g_h[s2*D + tid], v3 = g_h[s3*D + tid];
        acc = fmaxf(acc, v0 * w0);
        acc = fmaxf(acc, v1 * w1);
        acc = fmaxf(acc, v2 * w2);
        acc = fmaxf(acc, v3 * w3);
    }
    for (; i < end; i++)
        acc = fmaxf(acc, g_h[g_ssrc[i]*D + tid] * g_sw[i]);
    g_neigh[node*D + tid] = (beg == end) ? 0.f : acc;
}

// ---------------- GEMM1: g_h = feat @ W_pool^T + b_pool ----------------
// 128x128 tile, 256 threads, 8x8 per thread, K staged in 32-chunks.
__global__ __launch_bounds__(256) void gemm1_kernel(const float* __restrict__ feat,
                                                    const float* __restrict__ Wp,
                                                    const float* __restrict__ bias) {
    __shared__ __align__(16) float sA[32 * PADW];
    __shared__ __align__(16) float sB[32 * PADW];
    const int tid = threadIdx.x;
    const int tx = tid & 15, ty = tid >> 4;
    const int row0 = blockIdx.x * TM;

    float acc[8][8];
    {
        float b[8];
        #pragma unroll
        for (int j = 0; j < 4; j++) { b[j] = bias[tx*4 + j]; b[4+j] = bias[64 + tx*4 + j]; }
        #pragma unroll
        for (int i = 0; i < 8; i++)
            #pragma unroll
            for (int j = 0; j < 8; j++) acc[i][j] = b[j];
    }

    for (int k0 = 0; k0 < D; k0 += 32) {
        __syncthreads();
        #pragma unroll
        for (int t = tid; t < TM * 32; t += 256) {       // A tile (transposed to [k][m])
            int kk = t & 31, m = t >> 5;
            int row = row0 + m;
            sA[kk*PADW + m] = (row < N_NODES) ? feat[row*D + k0 + kk] : 0.f;
        }
        #pragma unroll
        for (int t = tid; t < 128 * 32; t += 256) {      // B tile: Wp[n][k]
            int kk = t & 31, n = t >> 5;
            sB[kk*PADW + n] = Wp[n*D + k0 + kk];
        }
        __syncthreads();
        #pragma unroll
        for (int kk = 0; kk < 32; kk++) {
            float4 va0 = *(const float4*)&sA[kk*PADW + ty*4];
            float4 va1 = *(const float4*)&sA[kk*PADW + 64 + ty*4];
            float4 vb0 = *(const float4*)&sB[kk*PADW + tx*4];
            float4 vb1 = *(const float4*)&sB[kk*PADW + 64 + tx*4];
            float a[8] = {va0.x, va0.y, va0.z, va0.w, va1.x, va1.y, va1.z, va1.w};
            float b[8] = {vb0.x, vb0.y, vb0.z, vb0.w, vb1.x, vb1.y, vb1.z, vb1.w};
            #pragma unroll
            for (int i = 0; i < 8; i++)
                #pragma unroll
                for (int j = 0; j < 8; j++) acc[i][j] = fmaf(a[i], b[j], acc[i][j]);
        }
    }
    #pragma unroll
    for (int i = 0; i < 8; i++) {
        int r = (i < 4) ? (ty*4 + i) : (64 + ty*4 + i - 4);
        int row = row0 + r;
        if (row < N_NODES) {
            *(float4*)&g_h[row*D + tx*4]      = make_float4(acc[i][0], acc[i][1], acc[i][2], acc[i][3]);
            *(float4*)&g_h[row*D + 64 + tx*4] = make_float4(acc[i][4], acc[i][5], acc[i][6], acc[i][7]);
        }
    }
}

// ---------------- GEMM2: out = concat(feat, g_neigh) @ W_neigh^T + b_neigh ----------------
__global__ __launch_bounds__(256) void gemm2_kernel(const float* __restrict__ feat,
                                                    const float* __restrict__ Wn,
                                                    const float* __restrict__ bias,
                                                    float* __restrict__ out) {
    __shared__ __align__(16) float sA[32 * PADW];
    __shared__ __align__(16) float sB[32 * PADW];
    const int tid = threadIdx.x;
    const int tx = tid & 15, ty = tid >> 4;
    const int row0 = blockIdx.x * TM;

    float acc[8][8];
    {
        float b[8];
        #pragma unroll
        for (int j = 0; j < 4; j++) { b[j] = bias[tx*4 + j]; b[4+j] = bias[64 + tx*4 + j]; }
        #pragma unroll
        for (int i = 0; i < 8; i++)
            #pragma unroll
            for (int j = 0; j < 8; j++) acc[i][j] = b[j];
    }

    for (int k0 = 0; k0 < K2; k0 += 32) {
        __syncthreads();
        const float* Asrc = (k0 < D) ? feat : g_neigh;
        const int    koff = (k0 < D) ? k0 : (k0 - D);
        #pragma unroll
        for (int t = tid; t < TM * 32; t += 256) {
            int kk = t & 31, m = t >> 5;
            int row = row0 + m;
            sA[kk*PADW + m] = (row < N_NODES) ? Asrc[row*D + koff + kk] : 0.f;
        }
        #pragma unroll
        for (int t = tid; t < 128 * 32; t += 256) {
            int kk = t & 31, n = t >> 5;
            sB[kk*PADW + n] = Wn[n*K2 + k0 + kk];
        }
        __syncthreads();
        #pragma unroll
        for (int kk = 0; kk < 32; kk++) {
            float4 va0 = *(const float4*)&sA[kk*PADW + ty*4];
            float4 va1 = *(const float4*)&sA[kk*PADW + 64 + ty*4];
            float4 vb0 = *(const float4*)&sB[kk*PADW + tx*4];
            float4 vb1 = *(const float4*)&sB[kk*PADW + 64 + tx*4];
            float a[8] = {va0.x, va0.y, va0.z, va0.w, va1.x, va1.y, va1.z, va1.w};
            float b[8] = {vb0.x, vb0.y, vb0.z, vb0.w, vb1.x, vb1.y, vb1.z, vb1.w};
            #pragma unroll
            for (int i = 0; i < 8; i++)
                #pragma unroll
                for (int j = 0; j < 8; j++) acc[i][j] = fmaf(a[i], b[j], acc[i][j]);
        }
    }
    #pragma unroll
    for (int i = 0; i < 8; i++) {
        int r = (i < 4) ? (ty*4 + i) : (64 + ty*4 + i - 4);
        int row = row0 + r;
        if (row < N_NODES) {
            *(float4*)&out[row*OUTF + tx*4]      = make_float4(acc[i][0], acc[i][1], acc[i][2], acc[i][3]);
            *(float4*)&out[row*OUTF + 64 + tx*4] = make_float4(acc[i][4], acc[i][5], acc[i][6], acc[i][7]);
        }
    }
}

// ---------------- launch ----------------
extern "C" void kernel_launch(void* const* d_in, const int* in_sizes, int n_in,
                              void* d_out, int out_size) {
    const float* feat    = (const float*)d_in[0];
    const float* weight  = (const float*)d_in[1];
    const int*   src     = (const int*)d_in[2];   // int32 (JAX x64 disabled)
    const int*   dst     = (const int*)d_in[3];
    const float* W_pool  = (const float*)d_in[4];
    const float* b_pool  = (const float*)d_in[5];
    const float* W_neigh = (const float*)d_in[6];
    const float* b_neigh = (const float*)d_in[7];
    float*       out     = (float*)d_out;

    const int GEMM_GRID = (N_NODES + TM - 1) / TM;   // 391

    zero_deg_kernel<<<(N_NODES + 255) / 256, 256>>>();
    hist_kernel<<<(N_EDGES + 255) / 256, 256>>>(dst);
    scan_kernel<<<1, 1024>>>();
    scatter_kernel<<<(N_EDGES + 255) / 256, 256>>>(src, dst, weight);

    gemm1_kernel<<<GEMM_GRID, 256>>>(feat, W_pool, b_pool);

    reduce_kernel<<<N_NODES, 128>>>();

    gemm2_kernel<<<GEMM_GRID, 256>>>(feat, W_neigh, b_neigh, out);
}

// round 9
// speedup vs baseline: 2.6380x; 1.4530x over previous
#include <cuda_runtime.h>
#include <cuda_bf16.h>
#include <mma.h>
#include <float.h>
#include <stdint.h>

using namespace nvcuda;

#define N_NODES 50000
#define N_PAD   50048          // 391 * 128: GEMM tiles store full tiles into g_h
#define N_EDGES 640000
#define D       128
#define OUTF    128
#define K2      256
#define TM      128
#define LDS_K   48             // bf16 row stride (48 elems = 96B, mult of 16B)

// ---------------- device scratch ----------------
__device__ __align__(16) float g_h[N_PAD * D];         // fc_pool output (padded)
__device__ __align__(16) float g_neigh[N_NODES * D];   // max-pooled messages
__device__ int   g_deg[N_NODES];
__device__ int   g_start[N_NODES + 1];
__device__ int   g_cursor[N_NODES];
__device__ __align__(16) int   g_ssrc[N_EDGES];
__device__ __align__(16) float g_sw[N_EDGES];

__device__ __forceinline__ int clampN(int v) { return min(max(v, 0), N_NODES - 1); }

// ---------------- CSR build (R4-verbatim) ----------------
__global__ void zero_deg_kernel() {
    int i = blockIdx.x * blockDim.x + threadIdx.x;
    if (i < N_NODES) g_deg[i] = 0;
}

__global__ void hist_kernel(const int* __restrict__ dst) {
    int e = blockIdx.x * blockDim.x + threadIdx.x;
    if (e < N_EDGES) atomicAdd(&g_deg[clampN(dst[e])], 1);
}

// R4-verbatim single-block scan (known-good)
__global__ void scan_kernel() {
    __shared__ int sh[1024];
    __shared__ int s_carry;
    int tid = threadIdx.x;
    if (tid == 0) s_carry = 0;
    __syncthreads();
    for (int base = 0; base < N_NODES; base += 1024) {
        int idx = base + tid;
        int v = (idx < N_NODES) ? g_deg[idx] : 0;
        sh[tid] = v;
        __syncthreads();
        #pragma unroll
        for (int off = 1; off < 1024; off <<= 1) {
            int t = (tid >= off) ? sh[tid - off] : 0;
            __syncthreads();
            sh[tid] += t;
            __syncthreads();
        }
        int excl = sh[tid] - v;
        int c = s_carry;
        if (idx < N_NODES) { g_start[idx] = c + excl; g_cursor[idx] = c + excl; }
        __syncthreads();
        if (tid == 1023) s_carry = c + sh[1023];
        __syncthreads();
    }
    if (tid == 0) g_start[N_NODES] = s_carry;
}

__global__ void scatter_kernel(const int* __restrict__ src, const int* __restrict__ dst,
                               const float* __restrict__ weight) {
    int e = blockIdx.x * blockDim.x + threadIdx.x;
    if (e >= N_EDGES) return;
    int d = clampN(dst[e]);
    int pos = atomicAdd(&g_cursor[d], 1);
    g_ssrc[pos] = clampN(src[e]);
    g_sw[pos]   = weight[e];
}

// ---------------- per-node max reduce (R4-verbatim, MLP=4) ----------------
__global__ __launch_bounds__(128) void reduce_kernel() {
    int node = blockIdx.x;
    int tid  = threadIdx.x;
    int beg = g_start[node], end = g_start[node + 1];
    float acc = -FLT_MAX;
    int i = beg;
    for (; i + 4 <= end; i += 4) {
        int   s0 = g_ssrc[i],   s1 = g_ssrc[i+1], s2 = g_ssrc[i+2], s3 = g_ssrc[i+3];
        float w0 = g_sw[i],     w1 = g_sw[i+1],   w2 = g_sw[i+2],   w3 = g_sw[i+3];
        float v0 = g_h[s0*D + tid], v1 = g_h[s1*D + tid];
        float v2 = g_h[s2*D + tid], v3 = g_h[s3*D + tid];
        acc = fmaxf(acc, v0 * w0);
        acc = fmaxf(acc, v1 * w1);
        acc = fmaxf(acc, v2 * w2);
        acc = fmaxf(acc, v3 * w3);
    }
    for (; i < end; i++)
        acc = fmaxf(acc, g_h[g_ssrc[i]*D + tid] * g_sw[i]);
    g_neigh[node*D + tid] = (beg == end) ? 0.f : acc;
}

// ---------------- wmma bf16 3-pass GEMM: out = A @ W^T + bias ----------------
// CTA: 128x128, 256 threads = 8 warps (4m x 2n), warp tile 32x64, K chunks of 32.
// D = AhiBhi + AloBhi + AhiBlo  (missing AloBlo ~ 2^-18 rel).
// TO_GH: write results to device-global g_h (device-code reference! passing the
// symbol as a host-side kernel arg yields the HOST shadow address, and GB300's
// ATS happily swallows the stores -- the R6-R8 bug).
static constexpr int SM_REG   = 128 * LDS_K;             // elems per bf16 region
static constexpr int SM_F_OFF = 4 * SM_REG * 2;          // 49152 bytes
static constexpr int SMEM_SZ  = SM_F_OFF + 16 * 128 * 4; // 57344 bytes

template<int KTOT, bool CONCAT, bool TO_GH>
__global__ __launch_bounds__(256) void gemm_wmma_kernel(const float* __restrict__ A0,
                                                        const float* __restrict__ W,
                                                        const float* __restrict__ bias,
                                                        float* __restrict__ outp) {
    extern __shared__ char smem[];
    __nv_bfloat16* sAhi = (__nv_bfloat16*)smem;
    __nv_bfloat16* sAlo = sAhi + SM_REG;
    __nv_bfloat16* sBhi = sAlo + SM_REG;
    __nv_bfloat16* sBlo = sBhi + SM_REG;
    float*         sF   = (float*)(smem + SM_F_OFF);     // bias tile / store staging

    const int tid  = threadIdx.x;
    const int lane = tid & 31;
    const int wid  = tid >> 5;
    const int wm   = wid >> 1;          // 0..3 -> rows wm*32
    const int wn   = wid & 1;           // 0..1 -> cols wn*64
    const int row0 = blockIdx.x * TM;

    float* dstp = TO_GH ? g_h : outp;   // device-side symbol reference

    // bias tile: 16 rows x 128 cols, every row = bias
    for (int i = tid; i < 16 * 128; i += 256) sF[i] = bias[i & 127];
    __syncthreads();

    wmma::fragment<wmma::accumulator, 16, 16, 16, float> acc[2][4];
    #pragma unroll
    for (int mt = 0; mt < 2; mt++)
        #pragma unroll
        for (int nt = 0; nt < 4; nt++)
            wmma::load_matrix_sync(acc[mt][nt], sF + wn * 64 + nt * 16, 128, wmma::mem_row_major);

    constexpr int NCHUNK = KTOT / 32;
    for (int c = 0; c < NCHUNK; c++) {
        const int k0 = c * 32;
        const float* Asrc = (!CONCAT || k0 < D) ? A0 : g_neigh;
        const int    koff = (!CONCAT || k0 < D) ? k0 : (k0 - D);
        __syncthreads();                 // prev chunk fully consumed

        #pragma unroll
        for (int t = 0; t < 4; t++) {    // A: 1024 granules of 4 floats
            int g = tid + t * 256;
            int row = g >> 3, kc = (g & 7) * 4;
            int grow = row0 + row;
            float4 v = (grow < N_NODES) ? *(const float4*)&Asrc[grow * D + koff + kc]
                                        : make_float4(0.f, 0.f, 0.f, 0.f);
            __nv_bfloat16 h0 = __float2bfloat16_rn(v.x), h1 = __float2bfloat16_rn(v.y);
            __nv_bfloat16 h2 = __float2bfloat16_rn(v.z), h3 = __float2bfloat16_rn(v.w);
            __nv_bfloat16 l0 = __float2bfloat16_rn(v.x - __bfloat162float(h0));
            __nv_bfloat16 l1 = __float2bfloat16_rn(v.y - __bfloat162float(h1));
            __nv_bfloat16 l2 = __float2bfloat16_rn(v.z - __bfloat162float(h2));
            __nv_bfloat16 l3 = __float2bfloat16_rn(v.w - __bfloat162float(h3));
            int o = row * LDS_K + kc;
            *(__nv_bfloat162*)&sAhi[o]     = __nv_bfloat162(h0, h1);
            *(__nv_bfloat162*)&sAhi[o + 2] = __nv_bfloat162(h2, h3);
            *(__nv_bfloat162*)&sAlo[o]     = __nv_bfloat162(l0, l1);
            *(__nv_bfloat162*)&sAlo[o + 2] = __nv_bfloat162(l2, l3);
        }
        #pragma unroll
        for (int t = 0; t < 4; t++) {    // B: W[n][k]
            int g = tid + t * 256;
            int row = g >> 3, kc = (g & 7) * 4;
            float4 v = *(const float4*)&W[row * KTOT + k0 + kc];
            __nv_bfloat16 h0 = __float2bfloat16_rn(v.x), h1 = __float2bfloat16_rn(v.y);
            __nv_bfloat16 h2 = __float2bfloat16_rn(v.z), h3 = __float2bfloat16_rn(v.w);
            __nv_bfloat16 l0 = __float2bfloat16_rn(v.x - __bfloat162float(h0));
            __nv_bfloat16 l1 = __float2bfloat16_rn(v.y - __bfloat162float(h1));
            __nv_bfloat16 l2 = __float2bfloat16_rn(v.z - __bfloat162float(h2));
            __nv_bfloat16 l3 = __float2bfloat16_rn(v.w - __bfloat162float(h3));
            int o = row * LDS_K + kc;
            *(__nv_bfloat162*)&sBhi[o]     = __nv_bfloat162(h0, h1);
            *(__nv_bfloat162*)&sBhi[o + 2] = __nv_bfloat162(h2, h3);
            *(__nv_bfloat162*)&sBlo[o]     = __nv_bfloat162(l0, l1);
            *(__nv_bfloat162*)&sBlo[o + 2] = __nv_bfloat162(l2, l3);
        }
        __syncthreads();

        #pragma unroll
        for (int ks = 0; ks < 2; ks++) {
            const int k16 = ks * 16;
            wmma::fragment<wmma::matrix_a, 16, 16, 16, __nv_bfloat16, wmma::row_major> ahi[2], alo[2];
            #pragma unroll
            for (int mt = 0; mt < 2; mt++) {
                int r = wm * 32 + mt * 16;
                wmma::load_matrix_sync(ahi[mt], &sAhi[r * LDS_K + k16], LDS_K);
                wmma::load_matrix_sync(alo[mt], &sAlo[r * LDS_K + k16], LDS_K);
            }
            #pragma unroll
            for (int nt = 0; nt < 4; nt++) {
                int n = wn * 64 + nt * 16;
                wmma::fragment<wmma::matrix_b, 16, 16, 16, __nv_bfloat16, wmma::col_major> bhi, blo;
                wmma::load_matrix_sync(bhi, &sBhi[n * LDS_K + k16], LDS_K);
                wmma::load_matrix_sync(blo, &sBlo[n * LDS_K + k16], LDS_K);
                #pragma unroll
                for (int mt = 0; mt < 2; mt++) {
                    wmma::mma_sync(acc[mt][nt], ahi[mt], bhi, acc[mt][nt]);
                    wmma::mma_sync(acc[mt][nt], alo[mt], bhi, acc[mt][nt]);
                    wmma::mma_sync(acc[mt][nt], ahi[mt], blo, acc[mt][nt]);
                }
            }
        }
    }

    // epilogue
    __syncthreads();                     // bias tile no longer needed -> staging reuse
    #pragma unroll
    for (int mt = 0; mt < 2; mt++) {
        int r0 = row0 + wm * 32 + mt * 16;
        #pragma unroll
        for (int nt = 0; nt < 4; nt++) {
            int c0 = wn * 64 + nt * 16;
            if (TO_GH || r0 + 16 <= N_NODES) {
                wmma::store_matrix_sync(&dstp[r0 * OUTF + c0], acc[mt][nt], OUTF, wmma::mem_row_major);
            } else {
                float* st = sF + wid * 256;     // private 16x16 staging per warp
                wmma::store_matrix_sync(st, acc[mt][nt], 16, wmma::mem_row_major);
                __syncwarp();
                for (int i = lane; i < 256; i += 32) {
                    int rr = r0 + (i >> 4);
                    if (rr < N_NODES) dstp[rr * OUTF + c0 + (i & 15)] = st[i];
                }
                __syncwarp();
            }
        }
    }
}

// ---------------- launch ----------------
extern "C" void kernel_launch(void* const* d_in, const int* in_sizes, int n_in,
                              void* d_out, int out_size) {
    const float* feat    = (const float*)d_in[0];
    const float* weight  = (const float*)d_in[1];
    const int*   src     = (const int*)d_in[2];
    const int*   dst     = (const int*)d_in[3];
    const float* W_pool  = (const float*)d_in[4];
    const float* b_pool  = (const float*)d_in[5];
    const float* W_neigh = (const float*)d_in[6];
    const float* b_neigh = (const float*)d_in[7];
    float*       out     = (float*)d_out;

    cudaFuncSetAttribute(gemm_wmma_kernel<D,  false, true>,
                         cudaFuncAttributeMaxDynamicSharedMemorySize, SMEM_SZ);
    cudaFuncSetAttribute(gemm_wmma_kernel<K2, true,  false>,
                         cudaFuncAttributeMaxDynamicSharedMemorySize, SMEM_SZ);

    const int GEMM_GRID = (N_NODES + TM - 1) / TM;   // 391

    zero_deg_kernel<<<(N_NODES + 255) / 256, 256>>>();
    hist_kernel<<<(N_EDGES + 255) / 256, 256>>>(dst);
    scan_kernel<<<1, 1024>>>();
    scatter_kernel<<<(N_EDGES + 255) / 256, 256>>>(src, dst, weight);

    // gemm1 writes g_h via in-kernel symbol reference (TO_GH=true)
    gemm_wmma_kernel<D, false, true><<<GEMM_GRID, 256, SMEM_SZ>>>(feat, W_pool, b_pool, nullptr);

    reduce_kernel<<<N_NODES, 128>>>();

    gemm_wmma_kernel<K2, true, false><<<GEMM_GRID, 256, SMEM_SZ>>>(feat, W_neigh, b_neigh, out);
}